// round 12
// baseline (speedup 1.0000x reference)
#include <cuda_runtime.h>
#include <cstdint>

#define NBMAX 2048
__device__ float g_partial[NBMAX];
__device__ unsigned g_count;

// diamond pseudo-angle in [-2,2], monotone in atan2(cy,cx)
__device__ __forceinline__ float pseudo_angle(float cx, float cy) {
    float den = fabsf(cx) + fabsf(cy);
    den = (den == 0.f) ? 1.f : den;
    return copysignf(1.f - __fdividef(cx, den), cy);
}

// monotone float->unsigned, low 3 bits replaced by index (stable tiebreak)
__device__ __forceinline__ unsigned okey(float pa, int i) {
    int ib = __float_as_int(pa);
    unsigned u = (unsigned)(ib ^ ((ib >> 31) | 0x80000000));
    return (u & 0xFFFFFFF8u) | (unsigned)i;
}

// Liang-Barsky clip of segment u + t*dd, t in [0,1], against |x|<=a, |y|<=b.
__device__ __forceinline__ float lb_span(float ux, float uy, float ix, float iy,
                                         float a, float b) {
    float lox = (-a - ux) * ix, hix = (a - ux) * ix;
    float loy = (-b - uy) * iy, hiy = (b - uy) * iy;
    float e0 = fminf(lox, hix), e1 = fmaxf(lox, hix);
    float f0 = fminf(loy, hiy), f1 = fmaxf(loy, hiy);
    float t0 = fmaxf(fmaxf(e0, f0), 0.f);
    float t1 = fminf(fminf(e1, f1), 1.f);
    return fmaxf(t1 - t0, 0.f);
}

__device__ __forceinline__ void cp4(uint32_t dst, const float* src, bool p) {
    if (p) asm volatile("cp.async.ca.shared.global [%0], [%1], 4;" :: "r"(dst), "l"(src));
}

// tile layout (floats): pred [0,1280) | target [1280,2560) | weight [2560,2816)
#define TILE_F 2816

__global__ void __launch_bounds__(256) poly_giou_kernel(const float* __restrict__ pred,
                                                        const float* __restrict__ target,
                                                        const float* __restrict__ weight,
                                                        float* __restrict__ out,
                                                        int N, int nblocks) {
    __shared__ float stile[2][TILE_F];
    __shared__ float2 gbuf[8][256];  // per-thread 8-point gather buffer

    const int tid = threadIdx.x;
    uint32_t sbase = (uint32_t)__cvta_generic_to_shared(&stile[0][0]);
    const int N5 = N * 5;

    int stride = gridDim.x * 256;
    int base0 = blockIdx.x * 256;

    // prologue: issue tile 0 loads
    {
        int e0 = base0 * 5;
        uint32_t sb = sbase;
#pragma unroll
        for (int i = 0; i < 5; i++) {
            int j = i * 256 + tid;
            cp4(sb + (unsigned)j * 4u, pred + e0 + j, e0 + j < N5);
            cp4(sb + (unsigned)(1280 + j) * 4u, target + e0 + j, e0 + j < N5);
        }
        cp4(sb + (unsigned)(2560 + tid) * 4u, weight + base0 + tid, base0 + tid < N);
        asm volatile("cp.async.commit_group;" ::: "memory");
    }

    float acc = 0.f;
    int buf = 0;
    for (int base = base0; base < N; base += stride) {
        asm volatile("cp.async.wait_group 0;" ::: "memory");
        __syncthreads();  // current tile visible to all; previous buffer free to overwrite

        // read this thread's item from smem tile
        int it = base + tid;
        const float* sp = &stile[buf][5 * tid];
        float p0 = sp[0], p1 = sp[1], p2 = sp[2], p3 = sp[3], p4 = sp[4];
        float t0_ = sp[1280], t1_ = sp[1281], t2 = sp[1282], t3 = sp[1283], t4 = sp[1284];
        float w = stile[buf][2560 + tid];

        // issue next tile into the other buffer (overlaps with compute below)
        int nxt = base + stride;
        if (nxt < N) {
            int e0 = nxt * 5;
            uint32_t sb = sbase + (unsigned)(buf ^ 1) * (TILE_F * 4u);
#pragma unroll
            for (int i = 0; i < 5; i++) {
                int j = i * 256 + tid;
                cp4(sb + (unsigned)j * 4u, pred + e0 + j, e0 + j < N5);
                cp4(sb + (unsigned)(1280 + j) * 4u, target + e0 + j, e0 + j < N5);
            }
            cp4(sb + (unsigned)(2560 + tid) * 4u, weight + nxt + tid, nxt + tid < N);
            asm volatile("cp.async.commit_group;" ::: "memory");
        }
        buf ^= 1;

        if (it < N) {
            // target frame: target = axis rect [-a,a]x[-b,b]
            float st, ct, sd, cd;
            __sincosf(t4, &st, &ct);
            __sincosf(p4 - t4, &sd, &cd);
            float rxx = p0 - t0_, ryy = p1 - t1_;
            float dx = ct * rxx + st * ryy;
            float dy = -st * rxx + ct * ryy;
            float a = 0.5f * t2, b = 0.5f * t3;
            float ah = 0.5f * p2, bh = 0.5f * p3;

            float rcd = __fdividef(1.f, cd), rsd = __fdividef(1.f, sd);
            float rp2 = __fdividef(1.f, p2), rp3 = __fdividef(1.f, p3);
            float rt2 = __fdividef(1.f, t2), rt3 = __fdividef(1.f, t3);

            // pred corners in target frame (symmetry: q2=2d-q0, q3=2d-q1)
            float A_ = ah * cd, B_ = bh * sd, C_ = ah * sd, D_ = bh * cd;
            float q0x = A_ - B_ + dx, q0y = C_ + D_ + dy;
            float q1x = -A_ - B_ + dx, q1y = -C_ + D_ + dy;
            float dx2 = dx + dx, dy2 = dy + dy;
            float q2x = dx2 - q0x, q2y = dy2 - q0y;
            float q3x = dx2 - q1x, q3y = dy2 - q1y;

            float twoI = 0.f;

            {   // pred edges clipped by target rect
                float d0x = -(A_ + A_), d0y = -(C_ + C_);   // -p2*cd, -p2*sd
                float d1x = B_ + B_, d1y = -(D_ + D_);      //  p3*sd, -p3*cd
                float i0x = -rp2 * rcd, i0y = -rp2 * rsd;
                float i1x = rp3 * rsd, i1y = -rp3 * rcd;
                float s0 = lb_span(q0x, q0y, i0x, i0y, a, b);
                float s1 = lb_span(q1x, q1y, i1x, i1y, a, b);
                float s2 = lb_span(q2x, q2y, -i0x, -i0y, a, b);
                float s3 = lb_span(q3x, q3y, -i1x, -i1y, a, b);
                twoI += s0 * (q0x * d0y - q0y * d0x);
                twoI += s1 * (q1x * d1y - q1y * d1x);
                twoI += s2 * (q2x * (-d0y) - q2y * (-d0x));
                twoI += s3 * (q3x * (-d1y) - q3y * (-d1x));
            }

            {   // target edges clipped by pred rect (pred frame) + frame correction
                float dpx = -(cd * dx + sd * dy);
                float dpy = sd * dx - cd * dy;
                float E_ = a * cd, F_ = b * sd, G_ = a * sd, H_ = b * cd;
                float u0x = E_ + F_ + dpx, u0y = -G_ + H_ + dpy;
                float u1x = -E_ + F_ + dpx, u1y = G_ + H_ + dpy;
                float dpx2 = dpx + dpx, dpy2 = dpy + dpy;
                float u2x = dpx2 - u0x, u2y = dpy2 - u0y;
                float u3x = dpx2 - u1x, u3y = dpy2 - u1y;
                float e0x = -(E_ + E_), e0y = G_ + G_;      // -t2*cd, t2*sd
                float e1x = -(F_ + F_), e1y = -(H_ + H_);   // -t3*sd, -t3*cd
                float j0x = -rt2 * rcd, j0y = rt2 * rsd;
                float j1x = -rt3 * rsd, j1y = -rt3 * rcd;
                float s0 = lb_span(u0x, u0y, j0x, j0y, ah, bh);
                float s1 = lb_span(u1x, u1y, j1x, j1y, ah, bh);
                float s2 = lb_span(u2x, u2y, -j0x, -j0y, ah, bh);
                float s3 = lb_span(u3x, u3y, -j1x, -j1y, ah, bh);
                twoI += s0 * (u0x * e0y - u0y * e0x);
                twoI += s1 * (u1x * e1y - u1y * e1x);
                twoI += s2 * (u2x * (-e0y) - u2y * (-e0x));
                twoI += s3 * (u3x * (-e1y) - u3y * (-e1x));
                float sdx = (s0 - s2) * e0x + (s1 - s3) * e1x;
                float sdy = (s0 - s2) * e0y + (s1 - s3) * e1y;
                float rsx = cd * sdx - sd * sdy;
                float rsy = sd * sdx + cd * sdy;
                twoI += dx * rsy - dy * rsx;
            }

            float overlap = fabsf(twoI) * 0.5f;

            // enclose: star polygon of 8 corners about exact centroid (dx/2, dy/2)
            float mx = 0.5f * dx, my = 0.5f * dy;
            float v0x = q0x - mx, v0y = q0y - my;
            float v1x = q1x - mx, v1y = q1y - my;
            float v2x = dx - v0x, v2y = dy - v0y;
            float v3x = dx - v1x, v3y = dy - v1y;
            float w0x = a - mx, w0y = b - my;
            float w1x = -a - mx, w1y = b - my;
            float w2x = -w0x - dx, w2y = -w0y - dy;
            float w3x = -w1x - dx, w3y = -w1y - dy;

            unsigned kk[8];
            gbuf[0][tid] = make_float2(v0x, v0y); kk[0] = okey(pseudo_angle(v0x, v0y), 0);
            gbuf[1][tid] = make_float2(v1x, v1y); kk[1] = okey(pseudo_angle(v1x, v1y), 1);
            gbuf[2][tid] = make_float2(v2x, v2y); kk[2] = okey(pseudo_angle(v2x, v2y), 2);
            gbuf[3][tid] = make_float2(v3x, v3y); kk[3] = okey(pseudo_angle(v3x, v3y), 3);
            gbuf[4][tid] = make_float2(w0x, w0y); kk[4] = okey(pseudo_angle(w0x, w0y), 4);
            gbuf[5][tid] = make_float2(w1x, w1y); kk[5] = okey(pseudo_angle(w1x, w1y), 5);
            gbuf[6][tid] = make_float2(w2x, w2y); kk[6] = okey(pseudo_angle(w2x, w2y), 6);
            gbuf[7][tid] = make_float2(w3x, w3y); kk[7] = okey(pseudo_angle(w3x, w3y), 7);

            // Batcher odd-even merge sort of keys, 19 ascending comparators
#define CE(I, J)                             \
            {                                \
                unsigned lo = min(kk[I], kk[J]); \
                unsigned hi = max(kk[I], kk[J]); \
                kk[I] = lo; kk[J] = hi;      \
            }
            CE(0, 1) CE(2, 3) CE(4, 5) CE(6, 7)
            CE(0, 2) CE(1, 3) CE(4, 6) CE(5, 7)
            CE(1, 2) CE(5, 6)
            CE(0, 4) CE(1, 5) CE(2, 6) CE(3, 7)
            CE(2, 4) CE(3, 5)
            CE(1, 2) CE(3, 4) CE(5, 6)
#undef CE

            float2 spt[8];
#pragma unroll
            for (int i = 0; i < 8; i++) spt[i] = gbuf[kk[i] & 7u][tid];
            float es = 0.f;
#pragma unroll
            for (int i = 0; i < 8; i++) {
                int j = (i + 1) & 7;
                es += spt[i].x * spt[j].y - spt[i].y * spt[j].x;
            }
            float enclose = fabsf(es) * 0.5f;

            float uni = p2 * p3 + t2 * t3 - overlap + 1e-6f;
            float iou = fmaxf(__fdividef(overlap, uni), 1e-6f);
            float loss = 2.f - iou - __fdividef(uni, enclose);
            acc += loss * w;
        }
    }

    // deterministic block reduction
    float v = acc;
#pragma unroll
    for (int o = 16; o > 0; o >>= 1) v += __shfl_down_sync(0xFFFFFFFFu, v, o);
    __shared__ float ws[8];
    __shared__ bool is_last;
    int lane = tid & 31;
    int wid = tid >> 5;
    if (lane == 0) ws[wid] = v;
    __syncthreads();
    if (wid == 0) {
        float t = (lane < 8) ? ws[lane] : 0.f;
#pragma unroll
        for (int o = 4; o > 0; o >>= 1) t += __shfl_down_sync(0xFFFFFFFFu, t, o);
        if (lane == 0) {
            g_partial[blockIdx.x] = t;
            __threadfence();
            unsigned old = atomicAdd(&g_count, 1u);
            is_last = (old == (unsigned)(nblocks - 1));
        }
    }
    __syncthreads();

    if (is_last) {
        __threadfence();
        double s = 0.0;
        for (int i = tid; i < nblocks; i += 256) s += (double)g_partial[i];
        __shared__ double sh[256];
        sh[tid] = s;
        __syncthreads();
#pragma unroll
        for (int o = 128; o > 0; o >>= 1) {
            if (tid < o) sh[tid] += sh[tid + o];
            __syncthreads();
        }
        if (tid == 0) {
            out[0] = (float)(sh[0] / (double)N);
            g_count = 0u;  // reset for next graph replay
        }
    }
}

extern "C" void kernel_launch(void* const* d_in, const int* in_sizes, int n_in,
                              void* d_out, int out_size) {
    const float* pred = (const float*)d_in[0];
    const float* target = (const float*)d_in[1];
    const float* weight = (const float*)d_in[2];
    int N = in_sizes[2];

    int threads = 256;
    // persistent single-wave grid: 148 SMs x 5 CTAs/SM
    int blocks = 148 * 5;
    int needed = (N + threads - 1) / threads;
    if (blocks > needed) blocks = needed;
    if (blocks > NBMAX) blocks = NBMAX;

    poly_giou_kernel<<<blocks, threads>>>(pred, target, weight, (float*)d_out, N, blocks);
}

// round 13
// speedup vs baseline: 1.1216x; 1.1216x over previous
#include <cuda_runtime.h>
#include <cstdint>

#define NBMAX 2048
__device__ float g_partial[NBMAX];
__device__ unsigned g_count;

// ---- packed f32x2 helpers (sm_100+/sm_103a) ----
__device__ __forceinline__ uint64_t PK(float x, float y) {
    uint64_t r;
    asm("mov.b64 %0, {%1, %2};" : "=l"(r) : "f"(x), "f"(y));
    return r;
}
__device__ __forceinline__ void UPK(uint64_t v, float& x, float& y) {
    asm("mov.b64 {%0, %1}, %2;" : "=f"(x), "=f"(y) : "l"(v));
}
__device__ __forceinline__ uint64_t SUB2(uint64_t a, uint64_t b) {
    uint64_t r; asm("sub.rn.f32x2 %0, %1, %2;" : "=l"(r) : "l"(a), "l"(b)); return r;
}
__device__ __forceinline__ uint64_t MUL2(uint64_t a, uint64_t b) {
    uint64_t r; asm("mul.rn.f32x2 %0, %1, %2;" : "=l"(r) : "l"(a), "l"(b)); return r;
}

// diamond pseudo-angle in [-2,2], monotone in atan2(cy,cx)
__device__ __forceinline__ float pseudo_angle(float cx, float cy) {
    float den = fabsf(cx) + fabsf(cy);
    den = (den == 0.f) ? 1.f : den;
    return copysignf(1.f - __fdividef(cx, den), cy);
}

// monotone float->unsigned, low 3 bits replaced by index (stable tiebreak)
__device__ __forceinline__ unsigned okey(float pa, int i) {
    int ib = __float_as_int(pa);
    unsigned u = (unsigned)(ib ^ ((ib >> 31) | 0x80000000));
    return (u & 0xFFFFFFF8u) | (unsigned)i;
}

// Packed Liang-Barsky: segment u + t*dd, t in [0,1], box |x|<=a,|y|<=b.
// u=(ux,uy), inv=(1/ddx,1/ddy), ab=(a,b), nab=(-a,-b) all packed f32x2.
__device__ __forceinline__ float lb_span2(uint64_t u, uint64_t inv, uint64_t ab, uint64_t nab) {
    uint64_t lo = MUL2(SUB2(nab, u), inv);
    uint64_t hi = MUL2(SUB2(ab, u), inv);
    float lox, loy, hix, hiy;
    UPK(lo, lox, loy);
    UPK(hi, hix, hiy);
    float e0 = fminf(lox, hix), e1 = fmaxf(lox, hix);
    float f0 = fminf(loy, hiy), f1 = fmaxf(loy, hiy);
    float t0 = fmaxf(fmaxf(e0, f0), 0.f);
    float t1 = fminf(fminf(e1, f1), 1.f);
    return fmaxf(t1 - t0, 0.f);
}

__global__ void __launch_bounds__(256) poly_giou_kernel(const float* __restrict__ pred,
                                                        const float* __restrict__ target,
                                                        const float* __restrict__ weight,
                                                        float* __restrict__ out,
                                                        int N, int nblocks) {
    __shared__ float2 gbuf[8][256];  // per-thread 8-point gather buffer

    const int tid = threadIdx.x;
    float acc = 0.f;
    int stride = gridDim.x * 256;
    for (int idx = blockIdx.x * 256 + tid; idx < N; idx += stride) {
        float p0 = pred[5 * idx + 0], p1 = pred[5 * idx + 1];
        float p2 = pred[5 * idx + 2], p3 = pred[5 * idx + 3], p4 = pred[5 * idx + 4];
        float t0_ = target[5 * idx + 0], t1_ = target[5 * idx + 1];
        float t2 = target[5 * idx + 2], t3 = target[5 * idx + 3], t4 = target[5 * idx + 4];

        // target frame: target = axis rect [-a,a]x[-b,b]; pred rotated by dd=p4-t4, centered at d
        float st, ct, sd, cd;
        __sincosf(t4, &st, &ct);
        __sincosf(p4 - t4, &sd, &cd);
        float rxx = p0 - t0_, ryy = p1 - t1_;
        float dx = ct * rxx + st * ryy;
        float dy = -st * rxx + ct * ryy;
        float a = 0.5f * t2, b = 0.5f * t3;
        float ah = 0.5f * p2, bh = 0.5f * p3;

        float rcd = __fdividef(1.f, cd), rsd = __fdividef(1.f, sd);
        float rp2 = __fdividef(1.f, p2), rp3 = __fdividef(1.f, p3);
        float rt2 = __fdividef(1.f, t2), rt3 = __fdividef(1.f, t3);

        // pred corners in target frame (symmetry: q2=2d-q0, q3=2d-q1)
        float A_ = ah * cd, B_ = bh * sd, C_ = ah * sd, D_ = bh * cd;
        float q0x = A_ - B_ + dx, q0y = C_ + D_ + dy;
        float q1x = -A_ - B_ + dx, q1y = -C_ + D_ + dy;
        float dx2 = dx + dx, dy2 = dy + dy;
        float q2x = dx2 - q0x, q2y = dy2 - q0y;
        float q3x = dx2 - q1x, q3y = dy2 - q1y;

        float twoI = 0.f;

        {   // pred edges clipped by target rect (target frame)
            float d0x = -(A_ + A_), d0y = -(C_ + C_);   // -p2*cd, -p2*sd
            float d1x = B_ + B_, d1y = -(D_ + D_);      //  p3*sd, -p3*cd
            float i0x = -rp2 * rcd, i0y = -rp2 * rsd;
            float i1x = rp3 * rsd, i1y = -rp3 * rcd;
            uint64_t ab = PK(a, b), nab = PK(-a, -b);
            uint64_t I0 = PK(i0x, i0y), I1 = PK(i1x, i1y);
            uint64_t nI0 = PK(-i0x, -i0y), nI1 = PK(-i1x, -i1y);
            float s0 = lb_span2(PK(q0x, q0y), I0, ab, nab);
            float s1 = lb_span2(PK(q1x, q1y), I1, ab, nab);
            float s2 = lb_span2(PK(q2x, q2y), nI0, ab, nab);
            float s3 = lb_span2(PK(q3x, q3y), nI1, ab, nab);
            twoI += s0 * (q0x * d0y - q0y * d0x);
            twoI += s1 * (q1x * d1y - q1y * d1x);
            twoI += s2 * (q2x * (-d0y) - q2y * (-d0x));
            twoI += s3 * (q3x * (-d1y) - q3y * (-d1x));
        }

        {   // target edges clipped by pred rect (pred frame) + frame correction
            float dpx = -(cd * dx + sd * dy);
            float dpy = sd * dx - cd * dy;
            float E_ = a * cd, F_ = b * sd, G_ = a * sd, H_ = b * cd;
            float u0x = E_ + F_ + dpx, u0y = -G_ + H_ + dpy;
            float u1x = -E_ + F_ + dpx, u1y = G_ + H_ + dpy;
            float dpx2 = dpx + dpx, dpy2 = dpy + dpy;
            float u2x = dpx2 - u0x, u2y = dpy2 - u0y;
            float u3x = dpx2 - u1x, u3y = dpy2 - u1y;
            float e0x = -(E_ + E_), e0y = G_ + G_;      // -t2*cd, t2*sd
            float e1x = -(F_ + F_), e1y = -(H_ + H_);   // -t3*sd, -t3*cd
            float j0x = -rt2 * rcd, j0y = rt2 * rsd;
            float j1x = -rt3 * rsd, j1y = -rt3 * rcd;
            uint64_t ab2 = PK(ah, bh), nab2 = PK(-ah, -bh);
            uint64_t J0 = PK(j0x, j0y), J1 = PK(j1x, j1y);
            uint64_t nJ0 = PK(-j0x, -j0y), nJ1 = PK(-j1x, -j1y);
            float s0 = lb_span2(PK(u0x, u0y), J0, ab2, nab2);
            float s1 = lb_span2(PK(u1x, u1y), J1, ab2, nab2);
            float s2 = lb_span2(PK(u2x, u2y), nJ0, ab2, nab2);
            float s3 = lb_span2(PK(u3x, u3y), nJ1, ab2, nab2);
            twoI += s0 * (u0x * e0y - u0y * e0x);
            twoI += s1 * (u1x * e1y - u1y * e1x);
            twoI += s2 * (u2x * (-e0y) - u2y * (-e0x));
            twoI += s3 * (u3x * (-e1y) - u3y * (-e1x));
            float sdx = (s0 - s2) * e0x + (s1 - s3) * e1x;
            float sdy = (s0 - s2) * e0y + (s1 - s3) * e1y;
            float rsx = cd * sdx - sd * sdy;
            float rsy = sd * sdx + cd * sdy;
            twoI += dx * rsy - dy * rsx;
        }

        float overlap = fabsf(twoI) * 0.5f;

        // enclose: star polygon of 8 corners about exact centroid (dx/2, dy/2)
        float mx = 0.5f * dx, my = 0.5f * dy;
        float v0x = q0x - mx, v0y = q0y - my;
        float v1x = q1x - mx, v1y = q1y - my;
        float v2x = dx - v0x, v2y = dy - v0y;
        float v3x = dx - v1x, v3y = dy - v1y;
        float w0x = a - mx, w0y = b - my;
        float w1x = -a - mx, w1y = b - my;
        float w2x = -w0x - dx, w2y = -w0y - dy;
        float w3x = -w1x - dx, w3y = -w1y - dy;

        unsigned kk[8];
        gbuf[0][tid] = make_float2(v0x, v0y); kk[0] = okey(pseudo_angle(v0x, v0y), 0);
        gbuf[1][tid] = make_float2(v1x, v1y); kk[1] = okey(pseudo_angle(v1x, v1y), 1);
        gbuf[2][tid] = make_float2(v2x, v2y); kk[2] = okey(pseudo_angle(v2x, v2y), 2);
        gbuf[3][tid] = make_float2(v3x, v3y); kk[3] = okey(pseudo_angle(v3x, v3y), 3);
        gbuf[4][tid] = make_float2(w0x, w0y); kk[4] = okey(pseudo_angle(w0x, w0y), 4);
        gbuf[5][tid] = make_float2(w1x, w1y); kk[5] = okey(pseudo_angle(w1x, w1y), 5);
        gbuf[6][tid] = make_float2(w2x, w2y); kk[6] = okey(pseudo_angle(w2x, w2y), 6);
        gbuf[7][tid] = make_float2(w3x, w3y); kk[7] = okey(pseudo_angle(w3x, w3y), 7);

        // Batcher odd-even merge sort of keys, 19 ascending comparators
#define CE(I, J)                             \
        {                                    \
            unsigned lo = min(kk[I], kk[J]); \
            unsigned hi = max(kk[I], kk[J]); \
            kk[I] = lo; kk[J] = hi;          \
        }
        CE(0, 1) CE(2, 3) CE(4, 5) CE(6, 7)
        CE(0, 2) CE(1, 3) CE(4, 6) CE(5, 7)
        CE(1, 2) CE(5, 6)
        CE(0, 4) CE(1, 5) CE(2, 6) CE(3, 7)
        CE(2, 4) CE(3, 5)
        CE(1, 2) CE(3, 4) CE(5, 6)
#undef CE

        // gather points in sorted order (same-thread STS->LDS, ordered, no syncs)
        float2 spt[8];
#pragma unroll
        for (int i = 0; i < 8; i++) spt[i] = gbuf[kk[i] & 7u][tid];
        float es = 0.f;
#pragma unroll
        for (int i = 0; i < 8; i++) {
            int j = (i + 1) & 7;
            es += spt[i].x * spt[j].y - spt[i].y * spt[j].x;  // translation-invariant shoelace
        }
        float enclose = fabsf(es) * 0.5f;

        float uni = p2 * p3 + t2 * t3 - overlap + 1e-6f;
        float iou = fmaxf(__fdividef(overlap, uni), 1e-6f);
        // loss = 1 - giou = 2 - iou - uni/enclose
        float loss = 2.f - iou - __fdividef(uni, enclose);
        acc += loss * weight[idx];
    }

    // deterministic block reduction
    float v = acc;
#pragma unroll
    for (int o = 16; o > 0; o >>= 1) v += __shfl_down_sync(0xFFFFFFFFu, v, o);
    __shared__ float ws[8];
    __shared__ bool is_last;
    int lane = tid & 31;
    int wid = tid >> 5;
    if (lane == 0) ws[wid] = v;
    __syncthreads();
    if (wid == 0) {
        float t = (lane < 8) ? ws[lane] : 0.f;
#pragma unroll
        for (int o = 4; o > 0; o >>= 1) t += __shfl_down_sync(0xFFFFFFFFu, t, o);
        if (lane == 0) {
            g_partial[blockIdx.x] = t;
            __threadfence();
            unsigned old = atomicAdd(&g_count, 1u);
            is_last = (old == (unsigned)(nblocks - 1));
        }
    }
    __syncthreads();

    if (is_last) {
        __threadfence();
        double s = 0.0;
        for (int i = tid; i < nblocks; i += 256) s += (double)g_partial[i];
        __shared__ double sh[256];
        sh[tid] = s;
        __syncthreads();
#pragma unroll
        for (int o = 128; o > 0; o >>= 1) {
            if (tid < o) sh[tid] += sh[tid + o];
            __syncthreads();
        }
        if (tid == 0) {
            out[0] = (float)(sh[0] / (double)N);
            g_count = 0u;  // reset for next graph replay
        }
    }
}

extern "C" void kernel_launch(void* const* d_in, const int* in_sizes, int n_in,
                              void* d_out, int out_size) {
    const float* pred = (const float*)d_in[0];
    const float* target = (const float*)d_in[1];
    const float* weight = (const float*)d_in[2];
    int N = in_sizes[2];

    int threads = 256;
    // persistent single-wave grid: 148 SMs x 5 CTAs/SM (48 regs, 256 thr)
    int blocks = 148 * 5;
    int needed = (N + threads - 1) / threads;
    if (blocks > needed) blocks = needed;
    if (blocks > NBMAX) blocks = NBMAX;

    poly_giou_kernel<<<blocks, threads>>>(pred, target, weight, (float*)d_out, N, blocks);
}